// round 2
// baseline (speedup 1.0000x reference)
#include <cuda_runtime.h>
#include <cuda_bf16.h>

// ---------------- problem constants ----------------
#define LDIM 1024
#define CZ   128
#define CS   1024
#define KSPL 3840            // 3*1280 split-K for final projection
#define ASTRIDE 136          // padded bf16 row stride (conflict-free LDS frags)

// ---------------- device scratch (no runtime alloc allowed) ----------------
__device__ __align__(16) float g_sc[LDIM * CZ];          // sum over m of z2  (per l)
__device__ __align__(16) float g_sr[LDIM * CZ];          // sum over l of z2  (per m)
__device__ float g_nc[LDIM];
__device__ float g_nr[LDIM];
__device__ __align__(16) __nv_bfloat16 g_w1b[CZ * ASTRIDE];
__device__ __align__(16) __nv_bfloat16 g_w2b[CZ * ASTRIDE];
__device__ __align__(16) __nv_bfloat16 g_wcb[(size_t)CS * KSPL];   // [hiW | loW | hiW]
__device__ __align__(16) __nv_bfloat16 g_catb[(size_t)LDIM * KSPL];// [hiA | hiA | loA]

// ---------------- mma helper ----------------
__device__ __forceinline__ void mma16816(float* d, const unsigned* a, const unsigned* b) {
    asm volatile(
        "mma.sync.aligned.m16n8k16.row.col.f32.bf16.bf16.f32 "
        "{%0,%1,%2,%3}, {%4,%5,%6,%7}, {%8,%9}, {%0,%1,%2,%3};\n"
        : "+f"(d[0]), "+f"(d[1]), "+f"(d[2]), "+f"(d[3])
        : "r"(a[0]), "r"(a[1]), "r"(a[2]), "r"(a[3]), "r"(b[0]), "r"(b[1]));
}

// 128x128x128 bf16 GEMM: A row-major [128][ASTRIDE], B = W [n][k] row-major [128][ASTRIDE]
__device__ __forceinline__ void gemm128(const __nv_bfloat16* __restrict__ A,
                                        const __nv_bfloat16* __restrict__ B,
                                        float d[2][8][4], int wm, int wn, int lane) {
#pragma unroll
    for (int kk = 0; kk < 8; ++kk) {
        const int k0 = kk * 16 + (lane & 3) * 2;
        unsigned a[2][4], b[8][2];
#pragma unroll
        for (int mt = 0; mt < 2; ++mt) {
            const int r = wm * 32 + mt * 16 + (lane >> 2);
            a[mt][0] = *(const unsigned*)(A + r * ASTRIDE + k0);
            a[mt][1] = *(const unsigned*)(A + (r + 8) * ASTRIDE + k0);
            a[mt][2] = *(const unsigned*)(A + r * ASTRIDE + k0 + 8);
            a[mt][3] = *(const unsigned*)(A + (r + 8) * ASTRIDE + k0 + 8);
        }
#pragma unroll
        for (int nt = 0; nt < 8; ++nt) {
            const int n = wn * 64 + nt * 8 + (lane >> 2);
            b[nt][0] = *(const unsigned*)(B + n * ASTRIDE + k0);
            b[nt][1] = *(const unsigned*)(B + n * ASTRIDE + k0 + 8);
        }
#pragma unroll
        for (int mt = 0; mt < 2; ++mt)
#pragma unroll
            for (int nt = 0; nt < 8; ++nt) mma16816(d[mt][nt], a[mt], b[nt]);
    }
}

// ---------------- prep kernels ----------------
__global__ void prep_w12(const float* __restrict__ w1, const float* __restrict__ w2) {
    int i = blockIdx.x * 256 + threadIdx.x;
    if (i >= CZ * ASTRIDE) return;
    int d = i / ASTRIDE, k = i % ASTRIDE;
    float v1 = (k < CZ) ? w1[d * CZ + k] : 0.f;
    float v2 = (k < CZ) ? w2[d * CZ + k] : 0.f;
    g_w1b[i] = __float2bfloat16(v1);
    g_w2b[i] = __float2bfloat16(v2);
}

__global__ void prep_wc(const float* __restrict__ wc) {
    int i = blockIdx.x * 256 + threadIdx.x;
    if (i >= CS * 1280) return;
    int d = i / 1280, k = i % 1280;
    float v = wc[i];
    __nv_bfloat16 hi = __float2bfloat16(v);
    __nv_bfloat16 lo = __float2bfloat16(v - __bfloat162float(hi));
    size_t base = (size_t)d * KSPL;
    g_wcb[base + k] = hi;
    g_wcb[base + 1280 + k] = lo;
    g_wcb[base + 2560 + k] = hi;
}

__global__ void zero_acc() {
    int i = blockIdx.x * 256 + threadIdx.x;
    if (i < LDIM * CZ) { g_sc[i] = 0.f; g_sr[i] = 0.f; }
}

__global__ void norm_kernel(const float* __restrict__ mask) {
    int b = blockIdx.x, t = threadIdx.x;   // grid 2048, block 128
    float s = 0.f;
    if (b < LDIM) {
        const float* p = mask + (size_t)b * LDIM;
        for (int m = t; m < LDIM; m += 128) s += p[m];
    } else {
        int m = b - LDIM;
        for (int l = t; l < LDIM; l += 128) s += mask[(size_t)l * LDIM + m];
    }
#pragma unroll
    for (int o = 16; o; o >>= 1) s += __shfl_xor_sync(0xffffffffu, s, o);
    __shared__ float ws[4];
    if ((t & 31) == 0) ws[t >> 5] = s;
    __syncthreads();
    if (t == 0) {
        float tot = ws[0] + ws[1] + ws[2] + ws[3];
        if (b < LDIM) g_nc[b] = tot; else g_nr[b - LDIM] = tot;
    }
}

// ---------------- main fused kernel: LN -> GEMM1 -> ReLU -> GEMM2 -> reductions ----------------
#define SMEM_MAIN (4 * CZ * ASTRIDE * 2 + 3 * CZ * 4)

__global__ __launch_bounds__(256, 1)
void main_kernel(const float* __restrict__ s_z, const float* __restrict__ mask,
                 const float* __restrict__ ln_g, const float* __restrict__ ln_b,
                 const float* __restrict__ b1p, const float* __restrict__ b2p) {
    extern __shared__ __align__(16) char smem_raw[];
    __nv_bfloat16* sA  = (__nv_bfloat16*)smem_raw;
    __nv_bfloat16* sH  = sA + CZ * ASTRIDE;
    __nv_bfloat16* sW1 = sH + CZ * ASTRIDE;
    __nv_bfloat16* sW2 = sW1 + CZ * ASTRIDE;
    float* sB1   = (float*)(sW2 + CZ * ASTRIDE);
    float* sB2   = sB1 + CZ;
    float* sMask = sB2 + CZ;

    const int tid = threadIdx.x, lane = tid & 31, wid = tid >> 5;
    const int wm = wid & 3, wn = wid >> 2;
    const int cta = blockIdx.x;                 // 144 CTAs = 8 mblks x 18 l-ranges
    const int mblk = cta / 18, sub = cta % 18;
    const int l0 = (sub * LDIM) / 18, l1 = ((sub + 1) * LDIM) / 18;
    const int m0 = mblk * 128;

    for (int i = tid; i < CZ * ASTRIDE / 4; i += 256) {
        ((uint2*)sW1)[i] = ((const uint2*)g_w1b)[i];
        ((uint2*)sW2)[i] = ((const uint2*)g_w2b)[i];
    }
    if (tid < CZ) { sB1[tid] = b1p[tid]; sB2[tid] = b2p[tid]; }
    const float4 gg = ((const float4*)ln_g)[lane];
    const float4 bb = ((const float4*)ln_b)[lane];

    float sr_acc[2][8][4];
#pragma unroll
    for (int mt = 0; mt < 2; ++mt)
#pragma unroll
        for (int nt = 0; nt < 8; ++nt)
#pragma unroll
            for (int j = 0; j < 4; ++j) sr_acc[mt][nt][j] = 0.f;

    for (int l = l0; l < l1; ++l) {
        __syncthreads();   // protect sA / sMask against previous iteration's readers
        if (tid < 32)
            ((float4*)sMask)[tid] = ((const float4*)(mask + (size_t)l * LDIM + m0))[tid];

        // ---- LayerNorm: 8 warps x 16 rows, each row = one (l,m) pair of 128 ch ----
        const float* zbase = s_z + (((size_t)l * LDIM + m0) << 7);
#pragma unroll 4
        for (int j = 0; j < 16; ++j) {
            const int row = wid * 16 + j;
            float4 x = ((const float4*)(zbase + ((size_t)row << 7)))[lane];
            float s = x.x + x.y + x.z + x.w;
            float q = fmaf(x.x, x.x, fmaf(x.y, x.y, fmaf(x.z, x.z, x.w * x.w)));
#pragma unroll
            for (int o = 16; o; o >>= 1) {
                s += __shfl_xor_sync(0xffffffffu, s, o);
                q += __shfl_xor_sync(0xffffffffu, q, o);
            }
            const float mu = s * (1.f / 128.f);
            const float var = q * (1.f / 128.f) - mu * mu;
            const float rstd = rsqrtf(var + 1e-5f);
            const float y0 = (x.x - mu) * rstd * gg.x + bb.x;
            const float y1 = (x.y - mu) * rstd * gg.y + bb.y;
            const float y2 = (x.z - mu) * rstd * gg.z + bb.z;
            const float y3 = (x.w - mu) * rstd * gg.w + bb.w;
            __nv_bfloat162 p0 = __floats2bfloat162_rn(y0, y1);
            __nv_bfloat162 p1 = __floats2bfloat162_rn(y2, y3);
            uint2 pk = make_uint2(*(unsigned*)&p0, *(unsigned*)&p1);
            *reinterpret_cast<uint2*>(sA + row * ASTRIDE + lane * 4) = pk;
        }
        __syncthreads();

        // ---- GEMM1 + bias + ReLU -> sH (bf16) ----
        float d1[2][8][4] = {};
        gemm128(sA, sW1, d1, wm, wn, lane);
#pragma unroll
        for (int mt = 0; mt < 2; ++mt)
#pragma unroll
            for (int nt = 0; nt < 8; ++nt) {
                const int r = wm * 32 + mt * 16 + (lane >> 2);
                const int c = wn * 64 + nt * 8 + (lane & 3) * 2;
                const float bv0 = sB1[c], bv1 = sB1[c + 1];
                const float h0 = fmaxf(d1[mt][nt][0] + bv0, 0.f);
                const float h1 = fmaxf(d1[mt][nt][1] + bv1, 0.f);
                const float h2 = fmaxf(d1[mt][nt][2] + bv0, 0.f);
                const float h3 = fmaxf(d1[mt][nt][3] + bv1, 0.f);
                *reinterpret_cast<__nv_bfloat162*>(sH + r * ASTRIDE + c) =
                    __floats2bfloat162_rn(h0, h1);
                *reinterpret_cast<__nv_bfloat162*>(sH + (r + 8) * ASTRIDE + c) =
                    __floats2bfloat162_rn(h2, h3);
            }
        __syncthreads();

        // ---- GEMM2 + bias + mask -> accumulate sr (regs) & sc (atomics) ----
        float d2[2][8][4] = {};
        gemm128(sH, sW2, d2, wm, wn, lane);

        float cs[8][2];
#pragma unroll
        for (int nt = 0; nt < 8; ++nt) { cs[nt][0] = 0.f; cs[nt][1] = 0.f; }
#pragma unroll
        for (int mt = 0; mt < 2; ++mt)
#pragma unroll
            for (int nt = 0; nt < 8; ++nt) {
                const int r = wm * 32 + mt * 16 + (lane >> 2);
                const int c = wn * 64 + nt * 8 + (lane & 3) * 2;
                const float mk0 = sMask[r], mk8 = sMask[r + 8];
                const float bv0 = sB2[c], bv1 = sB2[c + 1];
                const float v0 = (d2[mt][nt][0] + bv0) * mk0;
                const float v1 = (d2[mt][nt][1] + bv1) * mk0;
                const float v2 = (d2[mt][nt][2] + bv0) * mk8;
                const float v3 = (d2[mt][nt][3] + bv1) * mk8;
                sr_acc[mt][nt][0] += v0; sr_acc[mt][nt][1] += v1;
                sr_acc[mt][nt][2] += v2; sr_acc[mt][nt][3] += v3;
                cs[nt][0] += v0 + v2;
                cs[nt][1] += v1 + v3;
            }
#pragma unroll
        for (int nt = 0; nt < 8; ++nt) {
#pragma unroll
            for (int o = 4; o <= 16; o <<= 1) {
                cs[nt][0] += __shfl_xor_sync(0xffffffffu, cs[nt][0], o);
                cs[nt][1] += __shfl_xor_sync(0xffffffffu, cs[nt][1], o);
            }
        }
        if (lane < 4) {
#pragma unroll
            for (int nt = 0; nt < 8; ++nt) {
                const int c = wn * 64 + nt * 8 + lane * 2;
                atomicAdd(&g_sc[l * CZ + c], cs[nt][0]);
                atomicAdd(&g_sc[l * CZ + c + 1], cs[nt][1]);
            }
        }
    }

    // ---- flush per-m row sums ----
#pragma unroll
    for (int mt = 0; mt < 2; ++mt)
#pragma unroll
        for (int nt = 0; nt < 8; ++nt) {
            const int r = wm * 32 + mt * 16 + (lane >> 2);
            const int c = wn * 64 + nt * 8 + (lane & 3) * 2;
            atomicAdd(&g_sr[(size_t)(m0 + r) * CZ + c],     sr_acc[mt][nt][0]);
            atomicAdd(&g_sr[(size_t)(m0 + r) * CZ + c + 1], sr_acc[mt][nt][1]);
            atomicAdd(&g_sr[(size_t)(m0 + r + 8) * CZ + c],     sr_acc[mt][nt][2]);
            atomicAdd(&g_sr[(size_t)(m0 + r + 8) * CZ + c + 1], sr_acc[mt][nt][3]);
        }
}

// ---------------- build split-bf16 cat matrix ----------------
__global__ void cat_build(const float* __restrict__ s_s_in) {
    const int l = blockIdx.x;
    const float inc = 1.f / fmaxf(g_nc[l], 1.f);
    const float inr = 1.f / fmaxf(g_nr[l], 1.f);
    const size_t base = (size_t)l * KSPL;
    for (int k = threadIdx.x; k < 1280; k += 256) {
        float v;
        if (k < 128)        v = g_sc[l * CZ + k] * inc;
        else if (k < 256)   v = g_sr[l * CZ + (k - 128)] * inr;
        else                v = s_s_in[(size_t)l * CS + (k - 256)];
        __nv_bfloat16 hi = __float2bfloat16(v);
        __nv_bfloat16 lo = __float2bfloat16(v - __bfloat162float(hi));
        g_catb[base + k] = hi;
        g_catb[base + 1280 + k] = hi;
        g_catb[base + 2560 + k] = lo;
    }
}

// ---------------- final projection GEMM: [1024 x 3840] @ [1024 x 3840]^T ----------------
__device__ __forceinline__ void cp_async16(void* sptr, const void* gptr) {
    unsigned s = (unsigned)__cvta_generic_to_shared(sptr);
    asm volatile("cp.async.cg.shared.global [%0], [%1], 16;\n" :: "r"(s), "l"(gptr));
}

__global__ __launch_bounds__(256, 2)
void final_gemm(const float* __restrict__ bc, float* __restrict__ out) {
    __shared__ __align__(16) __nv_bfloat16 sA[2][64 * 72];
    __shared__ __align__(16) __nv_bfloat16 sB[2][64 * 72];
    const int tid = threadIdx.x, lane = tid & 31, wid = tid >> 5;
    const int wm = wid & 3, wn = wid >> 2;
    const int lbase = blockIdx.y * 64, dbase = blockIdx.x * 64;
    const int NCH = KSPL / 64;   // 60

    float acc[4][4];
#pragma unroll
    for (int nt = 0; nt < 4; ++nt)
#pragma unroll
        for (int j = 0; j < 4; ++j) acc[nt][j] = 0.f;

    // issue chunk 0
    {
        const size_t kb = 0;
        for (int i = tid; i < 512; i += 256) {
            int row = i >> 3, seg = i & 7;
            cp_async16(&sA[0][row * 72 + seg * 8], &g_catb[(size_t)(lbase + row) * KSPL + kb + seg * 8]);
            cp_async16(&sB[0][row * 72 + seg * 8], &g_wcb[(size_t)(dbase + row) * KSPL + kb + seg * 8]);
        }
        asm volatile("cp.async.commit_group;\n");
    }

    for (int ch = 0; ch < NCH; ++ch) {
        const int buf = ch & 1;
        if (ch + 1 < NCH) {
            const size_t kb = (size_t)(ch + 1) * 64;
            const int nb = buf ^ 1;
            for (int i = tid; i < 512; i += 256) {
                int row = i >> 3, seg = i & 7;
                cp_async16(&sA[nb][row * 72 + seg * 8], &g_catb[(size_t)(lbase + row) * KSPL + kb + seg * 8]);
                cp_async16(&sB[nb][row * 72 + seg * 8], &g_wcb[(size_t)(dbase + row) * KSPL + kb + seg * 8]);
            }
            asm volatile("cp.async.commit_group;\n");
            asm volatile("cp.async.wait_group 1;\n");
        } else {
            asm volatile("cp.async.wait_group 0;\n");
        }
        __syncthreads();
#pragma unroll
        for (int kk = 0; kk < 4; ++kk) {
            const int k0 = kk * 16 + (lane & 3) * 2;
            const int r = wm * 16 + (lane >> 2);
            unsigned a[4], b[4][2];
            a[0] = *(const unsigned*)&sA[buf][r * 72 + k0];
            a[1] = *(const unsigned*)&sA[buf][(r + 8) * 72 + k0];
            a[2] = *(const unsigned*)&sA[buf][r * 72 + k0 + 8];
            a[3] = *(const unsigned*)&sA[buf][(r + 8) * 72 + k0 + 8];
#pragma unroll
            for (int nt = 0; nt < 4; ++nt) {
                const int n = wn * 32 + nt * 8 + (lane >> 2);
                b[nt][0] = *(const unsigned*)&sB[buf][n * 72 + k0];
                b[nt][1] = *(const unsigned*)&sB[buf][n * 72 + k0 + 8];
            }
#pragma unroll
            for (int nt = 0; nt < 4; ++nt) mma16816(acc[nt], a, b[nt]);
        }
        __syncthreads();
    }

#pragma unroll
    for (int nt = 0; nt < 4; ++nt) {
        const int r = wm * 16 + (lane >> 2);
        const int c = wn * 32 + nt * 8 + (lane & 3) * 2;
        const int gr = lbase + r, gc = dbase + c;
        const float b0 = __ldg(&bc[gc]), b1v = __ldg(&bc[gc + 1]);
        out[(size_t)gr * CS + gc]           = acc[nt][0] + b0;
        out[(size_t)gr * CS + gc + 1]       = acc[nt][1] + b1v;
        out[(size_t)(gr + 8) * CS + gc]     = acc[nt][2] + b0;
        out[(size_t)(gr + 8) * CS + gc + 1] = acc[nt][3] + b1v;
    }
}

// ---------------- launcher ----------------
extern "C" void kernel_launch(void* const* d_in, const int* in_sizes, int n_in,
                              void* d_out, int out_size) {
    const float* s_z    = (const float*)d_in[0];
    const float* s_s_in = (const float*)d_in[1];
    const float* mask   = (const float*)d_in[2];
    const float* ln_g   = (const float*)d_in[3];
    const float* ln_b   = (const float*)d_in[4];
    const float* w1     = (const float*)d_in[5];
    const float* b1     = (const float*)d_in[6];
    const float* w2     = (const float*)d_in[7];
    const float* b2     = (const float*)d_in[8];
    const float* wc     = (const float*)d_in[9];
    const float* bc     = (const float*)d_in[10];
    float* out = (float*)d_out;
    (void)in_sizes; (void)n_in; (void)out_size;

    cudaFuncSetAttribute(main_kernel, cudaFuncAttributeMaxDynamicSharedMemorySize, SMEM_MAIN);

    prep_w12<<<(CZ * ASTRIDE + 255) / 256, 256>>>(w1, w2);
    prep_wc<<<(CS * 1280 + 255) / 256, 256>>>(wc);
    zero_acc<<<(LDIM * CZ + 255) / 256, 256>>>();
    norm_kernel<<<2048, 128>>>(mask);
    main_kernel<<<144, 256, SMEM_MAIN>>>(s_z, mask, ln_g, ln_b, b1, b2);
    cat_build<<<LDIM, 256>>>(s_s_in);
    final_gemm<<<dim3(16, 16), 256>>>(bc, out);
}